// round 16
// baseline (speedup 1.0000x reference)
#include <cuda_runtime.h>
#include <cuda_fp16.h>
#include <cstdint>

#define H_   32
#define W_   32
#define C_   512
#define CLS_ 1000
#define R_   64
#define B_   128
#define MROWS (B_ * C_)      // 65536
#define KDIM  1024           // W*H

// ---- GEMM tiling ----
#define TILE_M   128
#define KCHUNK   64          // fp16 per row = 128 B (one swizzle atom row)
#define NCHUNKS  16
// per-stage smem layout (bytes): A 16K | B 8K = 24K, x2 stages
#define A_OFF    0
#define B_OFF    16384
#define STAGE    24576
#define SMEM_DYN (2 * STAGE)   // 48 KB

#define SW(o) ((o) ^ (((o) >> 3) & 0x70))

// ---- static device scratch (no allocations allowed) ----
__device__ __align__(16) __half g_M[R_ * KDIM];   // [r][k] fp16 merged U2*U1
__device__ float g_part[512 * R_];                // per-CTA partials

// ===========================================================================
// PTX helpers — sm_80+ baseline only
// ===========================================================================
__device__ __forceinline__ uint32_t smem_u32(const void* p) {
    uint32_t a;
    asm("{ .reg .u64 t; cvta.to.shared.u64 t, %1; cvt.u32.u64 %0, t; }"
        : "=r"(a) : "l"(p));
    return a;
}
__device__ __forceinline__ void sts64(uint32_t a, uint32_t x, uint32_t y) {
    asm volatile("st.shared.v2.b32 [%0], {%1,%2};" :: "r"(a), "r"(x), "r"(y));
}
__device__ __forceinline__ void cpasync16(uint32_t dst, const void* src) {
    asm volatile("cp.async.cg.shared.global [%0], [%1], 16;"
                 :: "r"(dst), "l"(src));
}
__device__ __forceinline__ void cp_commit() {
    asm volatile("cp.async.commit_group;");
}
__device__ __forceinline__ void cp_wait0() {
    asm volatile("cp.async.wait_group 0;");
}
__device__ __forceinline__ void ldm4(uint32_t* r, uint32_t addr) {
    asm volatile("ldmatrix.sync.aligned.m8n8.x4.shared.b16 {%0,%1,%2,%3}, [%4];"
                 : "=r"(r[0]), "=r"(r[1]), "=r"(r[2]), "=r"(r[3]) : "r"(addr));
}
__device__ __forceinline__ void mma16816(float* c, const uint32_t* a, const uint32_t* b) {
    asm volatile(
        "mma.sync.aligned.m16n8k16.row.col.f32.f16.f16.f32 "
        "{%0,%1,%2,%3}, {%4,%5,%6,%7}, {%8,%9}, {%0,%1,%2,%3};"
        : "+f"(c[0]), "+f"(c[1]), "+f"(c[2]), "+f"(c[3])
        : "r"(a[0]), "r"(a[1]), "r"(a[2]), "r"(a[3]), "r"(b[0]), "r"(b[1]));
}

// ===========================================================================
// Kernel 0: M[r][k] = fp16( U2[w,r]*U1[h,r] ),  k = w*32+h
//   grid 32, block 256 — 8 elements per thread (one 16B STG), ILP=9 loads.
// ===========================================================================
__global__ __launch_bounds__(256) void build_M(const float* __restrict__ U1,
                                               const float* __restrict__ U2) {
    int idx8 = blockIdx.x * 256 + threadIdx.x;   // 0..8191, covers 8 k each
    int r  = idx8 >> 7;                          // 128 threads per r
    int k0 = (idx8 & 127) * 8;                   // 8-aligned -> single w
    int w  = k0 >> 5;
    int h0 = k0 & 31;
    float u2v = U2[w * R_ + r];
    float u1v[8];
#pragma unroll
    for (int j = 0; j < 8; j++)
        u1v[j] = U1[(h0 + j) * R_ + r];
    __half2 p[4];
#pragma unroll
    for (int j = 0; j < 4; j++)
        p[j] = __floats2half2_rn(u2v * u1v[2 * j], u2v * u1v[2 * j + 1]);
    *(uint4*)(g_M + r * KDIM + k0) = *(uint4*)p;
}

// ===========================================================================
// Kernel 1: pipelined fp16 mma.sync GEMM (128x64 tile, K=1024) + fused U3
//   row-reduce.  grid 512, block 256 (8 warps: 4m x 2n), dyn smem 48K.
//   Single barrier per chunk (R13 exact form — proven 65.2us total).
// ===========================================================================
__global__ __launch_bounds__(256, 2) void gemm_k(const float* __restrict__ x,
                                                 const float* __restrict__ U3) {
    extern __shared__ char dsm[];
    __shared__ float s_red[4][R_];

    const int tid  = threadIdx.x;
    const int wid  = tid >> 5;
    const int lane = tid & 31;
    const int m_warp = (wid >> 1) * 32;   // 0,32,64,96
    const int n_warp = (wid & 1) * 32;    // 0,32
    const long m0 = (long)blockIdx.x * TILE_M;

    const uint32_t sb = smem_u32(dsm);

    const int bn = tid >> 3;            // 0..31 (rows bn and bn+32)
    const int bj = tid & 7;             // 16B slot within 128B row
    const int rb = tid >> 4;            // 0..15
    const int f  = tid & 15;            // 0..15

    float acc[2][4][4];
#pragma unroll
    for (int i = 0; i < 2; i++)
#pragma unroll
        for (int j = 0; j < 4; j++)
#pragma unroll
            for (int e = 0; e < 4; e++) acc[i][j][e] = 0.0f;

    // ---- prologue: B chunk 0 via cp.async, A chunk 0 into registers ----
    {
#pragma unroll
        for (int it = 0; it < 2; it++) {
            int n = bn + it * 32;
            long go = (long)n * 2048 + bj * 16;      // k0 = 0
            uint32_t sw = SW((uint32_t)(n * 128 + bj * 16));
            cpasync16(sb + B_OFF + sw, (const char*)g_M + go);
        }
        cp_commit();
    }
    float4 pf[8];
    {
        const float* xg = x + m0 * KDIM;             // k0 = 0
#pragma unroll
        for (int it = 0; it < 8; it++)
            pf[it] = *(const float4*)(xg + (long)(rb + it * 16) * KDIM + f * 4);
    }

    for (int s = 0; s < NCHUNKS; s++) {
        const uint32_t bb = sb + (uint32_t)(s & 1) * STAGE;
        const uint32_t nb = sb + (uint32_t)((s + 1) & 1) * STAGE;

        // ---- convert prefetched A regs -> fp16 swizzled smem ----
#pragma unroll
        for (int it = 0; it < 8; it++) {
            float4 v = pf[it];
            __half h0 = __float2half_rn(v.x);
            __half h1 = __float2half_rn(v.y);
            __half h2 = __float2half_rn(v.z);
            __half h3 = __float2half_rn(v.w);
            uint32_t hA = (uint32_t)__half_as_ushort(h0) | ((uint32_t)__half_as_ushort(h1) << 16);
            uint32_t hB = (uint32_t)__half_as_ushort(h2) | ((uint32_t)__half_as_ushort(h3) << 16);
            uint32_t sw = SW((uint32_t)((rb + it * 16) * 128 + f * 8));
            sts64(bb + A_OFF + sw, hA, hB);
        }

        // ---- issue A LDG for chunk s+1 (completes under MMA) ----
        if (s < NCHUNKS - 1) {
            const float* xg = x + m0 * KDIM + (s + 1) * KCHUNK;
#pragma unroll
            for (int it = 0; it < 8; it++)
                pf[it] = *(const float4*)(xg + (long)(rb + it * 16) * KDIM + f * 4);
        }

        cp_wait0();          // B(s) landed (only outstanding group)
        __syncthreads();     // STS(s)+B(s) visible; MMA(s-1) complete everywhere

        // ---- issue B cp.async for chunk s+1 (stage (s+1)%2 now safe) ----
        if (s < NCHUNKS - 1) {
            const int k1 = (s + 1) * KCHUNK;
#pragma unroll
            for (int it = 0; it < 2; it++) {
                int n = bn + it * 32;
                long go = (long)n * 2048 + k1 * 2 + bj * 16;
                uint32_t sw = SW((uint32_t)(n * 128 + bj * 16));
                cpasync16(nb + B_OFF + sw, (const char*)g_M + go);
            }
            cp_commit();
        }

        // ---- compute: 4 k16-steps ----
#pragma unroll
        for (int kk = 0; kk < 4; kk++) {
            uint32_t ah[2][4], bhh[2][4];
#pragma unroll
            for (int mi = 0; mi < 2; mi++) {
                uint32_t row = m_warp + mi * 16 + (lane & 15);
                uint32_t kb  = kk * 32 + (lane >> 4) * 16;
                ldm4(ah[mi], bb + A_OFF + SW(row * 128 + kb));
            }
#pragma unroll
            for (int nq = 0; nq < 2; nq++) {
                uint32_t g = lane >> 3;
                uint32_t n = n_warp + nq * 16 + ((g >> 1) << 3) + (lane & 7);
                uint32_t kb = kk * 32 + (g & 1) * 16;
                ldm4(bhh[nq], bb + B_OFF + SW(n * 128 + kb));
            }
#pragma unroll
            for (int mi = 0; mi < 2; mi++)
#pragma unroll
                for (int nj = 0; nj < 4; nj++)
                    mma16816(acc[mi][nj], ah[mi], &bhh[nj >> 1][(nj & 1) * 2]);
        }
        // single barrier per chunk — next iteration's barrier provides the
        // write-after-read protection for stage s%2.
    }
    __syncthreads();   // MMA(15) (reads stage 1) done before s_u3 overwrites it

    // ---- epilogue: scale by U3[c,r], reduce 128 rows -> 64 partials ----
    float* s_u3 = (float*)dsm;                     // 32 KB, spans both stages
    const int c_base = (blockIdx.x & 3) * 128;
#pragma unroll
    for (int it = 0; it < 32; it++) {
        int idx = tid + it * 256;                  // 0..8191
        s_u3[idx] = U3[c_base * R_ + idx];
    }
    __syncthreads();

    float p[8];
#pragma unroll
    for (int j = 0; j < 8; j++) p[j] = 0.0f;
#pragma unroll
    for (int mi = 0; mi < 2; mi++)
#pragma unroll
        for (int pr = 0; pr < 2; pr++) {
            int rowl = m_warp + mi * 16 + pr * 8 + (lane >> 2);
            const float* w = s_u3 + rowl * R_;
#pragma unroll
            for (int nj = 0; nj < 4; nj++) {
                int col = n_warp + nj * 8 + (lane & 3) * 2;
                p[nj * 2 + 0] = fmaf(acc[mi][nj][pr * 2 + 0], w[col],     p[nj * 2 + 0]);
                p[nj * 2 + 1] = fmaf(acc[mi][nj][pr * 2 + 1], w[col + 1], p[nj * 2 + 1]);
            }
        }
#pragma unroll
    for (int o = 4; o < 32; o <<= 1)
#pragma unroll
        for (int j = 0; j < 8; j++)
            p[j] += __shfl_xor_sync(0xffffffffu, p[j], o);

    if (lane < 4) {
#pragma unroll
        for (int nj = 0; nj < 4; nj++) {
            int col = n_warp + nj * 8 + lane * 2;
            s_red[wid >> 1][col]     = p[nj * 2 + 0];
            s_red[wid >> 1][col + 1] = p[nj * 2 + 1];
        }
    }
    __syncthreads();
    if (tid < R_)
        g_part[blockIdx.x * R_ + tid] =
            s_red[0][tid] + s_red[1][tid] + s_red[2][tid] + s_red[3][tid];
}

// ===========================================================================
// Kernel 2: out[b,cls] = sum_r (sum_j part[4b+j,r]) * lam[r] * U4[cls,r]
//   grid 1024 = 8 class-chunks x 128 b, block 128 (4 warps).
//   Warp-per-class: ONE coalesced 256B row load per class (lane l covers
//   r = 2l, 2l+1), butterfly reduce. Fixes the 16x L1-wavefront inflation
//   of the one-class-per-thread layout.
// ===========================================================================
__global__ __launch_bounds__(128) void out_k(const float* __restrict__ lam,
                                             const float* __restrict__ U4,
                                             float* __restrict__ out) {
    const int b     = blockIdx.x & 127;     // 0..127
    const int chunk = blockIdx.x >> 7;      // 0..7
    const int tid   = threadIdx.x;
    const int wid   = tid >> 5;             // 0..3
    const int lane  = tid & 31;

    __shared__ float u[R_];
    if (tid < R_) {
        float s = g_part[(b * 4 + 0) * R_ + tid] + g_part[(b * 4 + 1) * R_ + tid]
                + g_part[(b * 4 + 2) * R_ + tid] + g_part[(b * 4 + 3) * R_ + tid];
        u[tid] = s * lam[tid];
    }
    __syncthreads();

    const float u0 = u[2 * lane];
    const float u1 = u[2 * lane + 1];
    const int cbase = chunk * 125;          // 8 x 125 = 1000

#pragma unroll 2
    for (int c = wid; c < 125; c += 4) {
        const int cls = cbase + c;
        float2 v = *(const float2*)(U4 + cls * R_ + 2 * lane);   // coalesced 256B/warp
        float p = fmaf(u1, v.y, u0 * v.x);
#pragma unroll
        for (int o = 16; o > 0; o >>= 1)
            p += __shfl_xor_sync(0xffffffffu, p, o);
        if (lane == 0) out[b * CLS_ + cls] = p;
    }
}

// ===========================================================================
extern "C" void kernel_launch(void* const* d_in, const int* in_sizes, int n_in,
                              void* d_out, int out_size) {
    const float* x   = (const float*)d_in[0];   // (B, C, W, H)
    const float* U1  = (const float*)d_in[1];   // (H, R)
    const float* U2  = (const float*)d_in[2];   // (W, R)
    const float* U3  = (const float*)d_in[3];   // (C, R)
    const float* U4  = (const float*)d_in[4];   // (CLS, R)
    const float* lam = (const float*)d_in[5];   // (R,)
    float* out = (float*)d_out;                 // (B, CLS)

    cudaFuncSetAttribute(gemm_k, cudaFuncAttributeMaxDynamicSharedMemorySize, SMEM_DYN);

    build_M<<<32, 256>>>(U1, U2);
    gemm_k<<<MROWS / TILE_M, 256, SMEM_DYN>>>(x, U3);
    out_k<<<1024, 128>>>(lam, U4, out);
}

// round 17
// speedup vs baseline: 1.1358x; 1.1358x over previous
#include <cuda_runtime.h>
#include <cuda_fp16.h>
#include <cstdint>

#define H_   32
#define W_   32
#define C_   512
#define CLS_ 1000
#define R_   64
#define B_   128
#define MROWS (B_ * C_)      // 65536
#define KDIM  1024           // W*H

// ---- GEMM tiling ----
#define TILE_M   128
#define KCHUNK   64          // fp16 per row = 128 B (one swizzle atom row)
#define NCHUNKS  16
// per-stage smem layout (bytes): A 16K | B 8K = 24K, x2 stages
#define A_OFF    0
#define B_OFF    16384
#define STAGE    24576
#define SMEM_DYN (2 * STAGE)   // 48 KB

#define SW(o) ((o) ^ (((o) >> 3) & 0x70))

// ---- static device scratch (no allocations allowed) ----
__device__ __align__(16) __half g_M[R_ * KDIM];   // [r][k] fp16 merged U2*U1
__device__ float g_part[512 * R_];                // per-CTA partials

// ===========================================================================
// PTX helpers — sm_80+ baseline only
// ===========================================================================
__device__ __forceinline__ uint32_t smem_u32(const void* p) {
    uint32_t a;
    asm("{ .reg .u64 t; cvta.to.shared.u64 t, %1; cvt.u32.u64 %0, t; }"
        : "=r"(a) : "l"(p));
    return a;
}
__device__ __forceinline__ void sts64(uint32_t a, uint32_t x, uint32_t y) {
    asm volatile("st.shared.v2.b32 [%0], {%1,%2};" :: "r"(a), "r"(x), "r"(y));
}
__device__ __forceinline__ void cpasync16(uint32_t dst, const void* src) {
    asm volatile("cp.async.cg.shared.global [%0], [%1], 16;"
                 :: "r"(dst), "l"(src));
}
__device__ __forceinline__ void cp_commit() {
    asm volatile("cp.async.commit_group;");
}
__device__ __forceinline__ void cp_wait0() {
    asm volatile("cp.async.wait_group 0;");
}
__device__ __forceinline__ void ldm4(uint32_t* r, uint32_t addr) {
    asm volatile("ldmatrix.sync.aligned.m8n8.x4.shared.b16 {%0,%1,%2,%3}, [%4];"
                 : "=r"(r[0]), "=r"(r[1]), "=r"(r[2]), "=r"(r[3]) : "r"(addr));
}
__device__ __forceinline__ void mma16816(float* c, const uint32_t* a, const uint32_t* b) {
    asm volatile(
        "mma.sync.aligned.m16n8k16.row.col.f32.f16.f16.f32 "
        "{%0,%1,%2,%3}, {%4,%5,%6,%7}, {%8,%9}, {%0,%1,%2,%3};"
        : "+f"(c[0]), "+f"(c[1]), "+f"(c[2]), "+f"(c[3])
        : "r"(a[0]), "r"(a[1]), "r"(a[2]), "r"(a[3]), "r"(b[0]), "r"(b[1]));
}

// ===========================================================================
// Kernel 0: M[r][k] = fp16( U2[w,r]*U1[h,r] ),  k = w*32+h
//   grid 32, block 256 — 8 elements per thread (one 16B STG), ILP=9 loads.
// ===========================================================================
__global__ __launch_bounds__(256) void build_M(const float* __restrict__ U1,
                                               const float* __restrict__ U2) {
    int idx8 = blockIdx.x * 256 + threadIdx.x;   // 0..8191, covers 8 k each
    int r  = idx8 >> 7;                          // 128 threads per r
    int k0 = (idx8 & 127) * 8;                   // 8-aligned -> single w
    int w  = k0 >> 5;
    int h0 = k0 & 31;
    float u2v = U2[w * R_ + r];
    float u1v[8];
#pragma unroll
    for (int j = 0; j < 8; j++)
        u1v[j] = U1[(h0 + j) * R_ + r];
    __half2 p[4];
#pragma unroll
    for (int j = 0; j < 4; j++)
        p[j] = __floats2half2_rn(u2v * u1v[2 * j], u2v * u1v[2 * j + 1]);
    *(uint4*)(g_M + r * KDIM + k0) = *(uint4*)p;
}

// ===========================================================================
// Kernel 1: pipelined fp16 mma.sync GEMM (128x64 tile, K=1024) + fused U3
//   row-reduce.  grid 512, block 256 (8 warps: 4m x 2n), dyn smem 48K.
//   Single barrier per chunk (R13 exact form).
// ===========================================================================
__global__ __launch_bounds__(256, 2) void gemm_k(const float* __restrict__ x,
                                                 const float* __restrict__ U3) {
    extern __shared__ char dsm[];
    __shared__ float s_red[4][R_];

    const int tid  = threadIdx.x;
    const int wid  = tid >> 5;
    const int lane = tid & 31;
    const int m_warp = (wid >> 1) * 32;   // 0,32,64,96
    const int n_warp = (wid & 1) * 32;    // 0,32
    const long m0 = (long)blockIdx.x * TILE_M;

    const uint32_t sb = smem_u32(dsm);

    const int bn = tid >> 3;            // 0..31 (rows bn and bn+32)
    const int bj = tid & 7;             // 16B slot within 128B row
    const int rb = tid >> 4;            // 0..15
    const int f  = tid & 15;            // 0..15

    float acc[2][4][4];
#pragma unroll
    for (int i = 0; i < 2; i++)
#pragma unroll
        for (int j = 0; j < 4; j++)
#pragma unroll
            for (int e = 0; e < 4; e++) acc[i][j][e] = 0.0f;

    // ---- prologue: B chunk 0 via cp.async, A chunk 0 into registers ----
    {
#pragma unroll
        for (int it = 0; it < 2; it++) {
            int n = bn + it * 32;
            long go = (long)n * 2048 + bj * 16;      // k0 = 0
            uint32_t sw = SW((uint32_t)(n * 128 + bj * 16));
            cpasync16(sb + B_OFF + sw, (const char*)g_M + go);
        }
        cp_commit();
    }
    float4 pf[8];
    {
        const float* xg = x + m0 * KDIM;             // k0 = 0
#pragma unroll
        for (int it = 0; it < 8; it++)
            pf[it] = *(const float4*)(xg + (long)(rb + it * 16) * KDIM + f * 4);
    }

    for (int s = 0; s < NCHUNKS; s++) {
        const uint32_t bb = sb + (uint32_t)(s & 1) * STAGE;
        const uint32_t nb = sb + (uint32_t)((s + 1) & 1) * STAGE;

        // ---- convert prefetched A regs -> fp16 swizzled smem ----
#pragma unroll
        for (int it = 0; it < 8; it++) {
            float4 v = pf[it];
            __half h0 = __float2half_rn(v.x);
            __half h1 = __float2half_rn(v.y);
            __half h2 = __float2half_rn(v.z);
            __half h3 = __float2half_rn(v.w);
            uint32_t hA = (uint32_t)__half_as_ushort(h0) | ((uint32_t)__half_as_ushort(h1) << 16);
            uint32_t hB = (uint32_t)__half_as_ushort(h2) | ((uint32_t)__half_as_ushort(h3) << 16);
            uint32_t sw = SW((uint32_t)((rb + it * 16) * 128 + f * 8));
            sts64(bb + A_OFF + sw, hA, hB);
        }

        // ---- issue A LDG for chunk s+1 (completes under MMA) ----
        if (s < NCHUNKS - 1) {
            const float* xg = x + m0 * KDIM + (s + 1) * KCHUNK;
#pragma unroll
            for (int it = 0; it < 8; it++)
                pf[it] = *(const float4*)(xg + (long)(rb + it * 16) * KDIM + f * 4);
        }

        cp_wait0();          // B(s) landed (only outstanding group)
        __syncthreads();     // STS(s)+B(s) visible; MMA(s-1) complete everywhere

        // ---- issue B cp.async for chunk s+1 (stage (s+1)%2 now safe) ----
        if (s < NCHUNKS - 1) {
            const int k1 = (s + 1) * KCHUNK;
#pragma unroll
            for (int it = 0; it < 2; it++) {
                int n = bn + it * 32;
                long go = (long)n * 2048 + k1 * 2 + bj * 16;
                uint32_t sw = SW((uint32_t)(n * 128 + bj * 16));
                cpasync16(nb + B_OFF + sw, (const char*)g_M + go);
            }
            cp_commit();
        }

        // ---- compute: 4 k16-steps ----
#pragma unroll
        for (int kk = 0; kk < 4; kk++) {
            uint32_t ah[2][4], bhh[2][4];
#pragma unroll
            for (int mi = 0; mi < 2; mi++) {
                uint32_t row = m_warp + mi * 16 + (lane & 15);
                uint32_t kb  = kk * 32 + (lane >> 4) * 16;
                ldm4(ah[mi], bb + A_OFF + SW(row * 128 + kb));
            }
#pragma unroll
            for (int nq = 0; nq < 2; nq++) {
                uint32_t g = lane >> 3;
                uint32_t n = n_warp + nq * 16 + ((g >> 1) << 3) + (lane & 7);
                uint32_t kb = kk * 32 + (g & 1) * 16;
                ldm4(bhh[nq], bb + B_OFF + SW(n * 128 + kb));
            }
#pragma unroll
            for (int mi = 0; mi < 2; mi++)
#pragma unroll
                for (int nj = 0; nj < 4; nj++)
                    mma16816(acc[mi][nj], ah[mi], &bhh[nj >> 1][(nj & 1) * 2]);
        }
        // single barrier per chunk — next iteration's barrier provides the
        // write-after-read protection for stage s%2.
    }
    __syncthreads();   // MMA(15) (reads stage 1) done before s_u3 overwrites it

    // ---- epilogue: scale by U3[c,r], reduce 128 rows -> 64 partials ----
    float* s_u3 = (float*)dsm;                     // 32 KB, spans both stages
    const int c_base = (blockIdx.x & 3) * 128;
#pragma unroll
    for (int it = 0; it < 32; it++) {
        int idx = tid + it * 256;                  // 0..8191
        s_u3[idx] = U3[c_base * R_ + idx];
    }
    __syncthreads();

    float p[8];
#pragma unroll
    for (int j = 0; j < 8; j++) p[j] = 0.0f;
#pragma unroll
    for (int mi = 0; mi < 2; mi++)
#pragma unroll
        for (int pr = 0; pr < 2; pr++) {
            int rowl = m_warp + mi * 16 + pr * 8 + (lane >> 2);
            const float* w = s_u3 + rowl * R_;
#pragma unroll
            for (int nj = 0; nj < 4; nj++) {
                int col = n_warp + nj * 8 + (lane & 3) * 2;
                p[nj * 2 + 0] = fmaf(acc[mi][nj][pr * 2 + 0], w[col],     p[nj * 2 + 0]);
                p[nj * 2 + 1] = fmaf(acc[mi][nj][pr * 2 + 1], w[col + 1], p[nj * 2 + 1]);
            }
        }
#pragma unroll
    for (int o = 4; o < 32; o <<= 1)
#pragma unroll
        for (int j = 0; j < 8; j++)
            p[j] += __shfl_xor_sync(0xffffffffu, p[j], o);

    if (lane < 4) {
#pragma unroll
        for (int nj = 0; nj < 4; nj++) {
            int col = n_warp + nj * 8 + lane * 2;
            s_red[wid >> 1][col]     = p[nj * 2 + 0];
            s_red[wid >> 1][col + 1] = p[nj * 2 + 1];
        }
    }
    __syncthreads();
    if (tid < R_)
        g_part[blockIdx.x * R_ + tid] =
            s_red[0][tid] + s_red[1][tid] + s_red[2][tid] + s_red[3][tid];
}

// ===========================================================================
// Kernel 2: out[b,cls] = sum_r (sum_j part[4b+j,r]) * lam[r] * U4[cls,r]
//   grid 1024 = 8 class-chunks x 128 b, block 128.
//   U4 chunk staged through smem (coalesced LDG, pad-65 conflict-free LDS),
//   then one class per thread from smem.
// ===========================================================================
__global__ __launch_bounds__(128) void out_k(const float* __restrict__ lam,
                                             const float* __restrict__ U4,
                                             float* __restrict__ out) {
    extern __shared__ float s4[];           // 125 * 65 floats = 32500 B
    __shared__ float u[R_];

    const int b     = blockIdx.x & 127;     // 0..127
    const int chunk = blockIdx.x >> 7;      // 0..7
    const int tid   = threadIdx.x;
    const int cbase = chunk * 125;          // 8 x 125 = 1000

    if (tid < R_) {
        float s = g_part[(b * 4 + 0) * R_ + tid] + g_part[(b * 4 + 1) * R_ + tid]
                + g_part[(b * 4 + 2) * R_ + tid] + g_part[(b * 4 + 3) * R_ + tid];
        u[tid] = s * lam[tid];
    }

    // ---- stage U4 chunk: 125 rows x 64 floats, coalesced float4 LDG ----
#pragma unroll
    for (int it = 0; it < 16; it++) {
        int i = tid + it * 128;             // 0..2047 float4 slots (need 2000)
        if (i < 125 * 16) {
            int cl = i >> 4;                // 0..124
            int rq = (i & 15) * 4;          // 0..60
            float4 v = *(const float4*)(U4 + (cbase + cl) * R_ + rq);
            float* dst = &s4[cl * 65 + rq];
            dst[0] = v.x; dst[1] = v.y; dst[2] = v.z; dst[3] = v.w;
        }
    }
    __syncthreads();

    if (tid < 125) {
        const float* row = &s4[tid * 65];   // bank (tid + r) % 32: conflict-free
        float s = 0.0f;
#pragma unroll
        for (int r = 0; r < R_; r++)
            s = fmaf(u[r], row[r], s);      // u[r]: warp broadcast
        out[b * CLS_ + cbase + tid] = s;
    }
}

// ===========================================================================
extern "C" void kernel_launch(void* const* d_in, const int* in_sizes, int n_in,
                              void* d_out, int out_size) {
    const float* x   = (const float*)d_in[0];   // (B, C, W, H)
    const float* U1  = (const float*)d_in[1];   // (H, R)
    const float* U2  = (const float*)d_in[2];   // (W, R)
    const float* U3  = (const float*)d_in[3];   // (C, R)
    const float* U4  = (const float*)d_in[4];   // (CLS, R)
    const float* lam = (const float*)d_in[5];   // (R,)
    float* out = (float*)d_out;                 // (B, CLS)

    cudaFuncSetAttribute(gemm_k, cudaFuncAttributeMaxDynamicSharedMemorySize, SMEM_DYN);

    build_M<<<32, 256>>>(U1, U2);
    gemm_k<<<MROWS / TILE_M, 256, SMEM_DYN>>>(x, U3);
    out_k<<<1024, 128, 125 * 65 * sizeof(float)>>>(lam, U4, out);
}